// round 3
// baseline (speedup 1.0000x reference)
#include <cuda_runtime.h>
#include <climits>

#define Bn 64
#define Hn 512
#define Wn 512
#define HWn (Hn * Wn)
#define HW4 (HWn / 4)
#define ROWS_PER_BLOCK 8
#define BLOCKS_PER_BATCH (Hn / ROWS_PER_BLOCK)   // 64
#define GRID (Bn * BLOCKS_PER_BATCH)             // 4096

// Per-block partials — fully overwritten every launch before being read.
// Counter self-resets (last block zeroes it): deterministic across replays.
__device__ float    g_ps1[GRID];
__device__ float    g_ps2[GRID];
__device__ unsigned g_pflags[GRID];   // 16 bits: row r in block -> bits 2r (cup), 2r+1 (disc)
__device__ unsigned g_count[Bn];

__global__ void __launch_bounds__(256) cdr_fused_kernel(const float* __restrict__ x,
                                                        float* __restrict__ out) {
    const int b     = blockIdx.x >> 6;      // batch
    const int quad8 = blockIdx.x & 63;      // which group of 8 rows
    const int tid   = threadIdx.x;

    // ---- Phase 1: streaming loads (12x LDG.128, front-batched, evict-first) ----
    const float4* p = (const float4*)x;
    // block region: 8 rows = 1024 float4 per channel; thread handles idx tid + 256*j
    const size_t base4 = (((size_t)b * 3 * HWn + (size_t)quad8 * ROWS_PER_BLOCK * Wn) >> 2)
                       + (size_t)tid;

    float4 v[3][4];
#pragma unroll
    for (int c = 0; c < 3; c++)
#pragma unroll
        for (int j = 0; j < 4; j++)
            v[c][j] = __ldcs(p + base4 + (size_t)c * HW4 + j * 256);

    float s1 = 0.f, s2 = 0.f;
    unsigned amask = 0;   // bit j: label1 seen in chunk j; bit j+4: label2 seen in chunk j

#pragma unroll
    for (int j = 0; j < 4; j++) {
        const float* a0p = (const float*)&v[0][j];
        const float* a1p = (const float*)&v[1][j];
        const float* a2p = (const float*)&v[2][j];
        bool any1 = false, any2 = false;
#pragma unroll
        for (int k = 0; k < 4; k++) {
            float a0 = a0p[k], a1 = a1p[k], a2 = a2p[k];

            // argmax, first-occurrence tie semantics (strict >)
            float m01 = fmaxf(a0, a1);
            bool  l1  = a1 > a0;
            bool  l2  = a2 > m01;
            any1 |= (l1 && !l2);
            any2 |= l2;

            // softmax p1,p2 pivoted on a1: 2x EX2 + 1x RCP
            float e0  = __expf(a0 - a1);
            float e2  = __expf(a2 - a1);
            float inv = __fdividef(1.0f, e0 + 1.0f + e2);
            s1 += inv;        // p(channel 1) = cup
            s2 += e2 * inv;   // p(channel 2) = disc
        }
        amask |= (any1 ? (1u << j) : 0u) | (any2 ? (1u << (j + 4)) : 0u);
    }

    // ---- Phase 2: deterministic in-warp reduction ----
#pragma unroll
    for (int o = 16; o > 0; o >>= 1) {
        s1 += __shfl_xor_sync(0xFFFFFFFFu, s1, o);
        s2 += __shfl_xor_sync(0xFFFFFFFFu, s2, o);
        amask |= __shfl_xor_sync(0xFFFFFFFFu, amask, o);
    }

    // Map warp's per-chunk flags to the block's 16-bit row mask.
    // chunk j of warp w lives in row 2j + (w>>2)  (w in 0..7)
    const int wid = tid >> 5, lid = tid & 31;
    unsigned wrowmask = 0;
#pragma unroll
    for (int j = 0; j < 4; j++) {
        int r = 2 * j + (wid >> 2);
        wrowmask |= ((amask >> j) & 1u) << (2 * r);
        wrowmask |= ((amask >> (j + 4)) & 1u) << (2 * r + 1);
    }

    __shared__ float    sw1[8], sw2[8];
    __shared__ unsigned swf[8];
    if (lid == 0) { sw1[wid] = s1; sw2[wid] = s2; swf[wid] = wrowmask; }
    __syncthreads();

    if (tid == 0) {
        float bs1 = 0.f, bs2 = 0.f;
        unsigned fw = 0;
#pragma unroll
        for (int w = 0; w < 8; w++) { bs1 += sw1[w]; bs2 += sw2[w]; fw |= swf[w]; }
        g_ps1[blockIdx.x]    = bs1;
        g_ps2[blockIdx.x]    = bs2;
        g_pflags[blockIdx.x] = fw;
    }

    // ---- Phase 3: last block of each batch finalizes ----
    __shared__ int lastFlag;
    if (tid == 0) {
        __threadfence();
        lastFlag = (atomicAdd(&g_count[b], 1u) == BLOCKS_PER_BATCH - 1);
    }
    __syncthreads();
    if (!lastFlag) return;

    float v1 = 0.f, v2 = 0.f;
    int   mn1 = INT_MAX, mx1 = -1, mn2 = INT_MAX, mx2 = -1;
    if (tid < BLOCKS_PER_BATCH) {
        int idx = b * BLOCKS_PER_BATCH + tid;
        v1 = g_ps1[idx];
        v2 = g_ps2[idx];
        unsigned fl = g_pflags[idx];
#pragma unroll
        for (int r = 0; r < ROWS_PER_BLOCK; r++) {
            int rr = tid * ROWS_PER_BLOCK + r;
            if (fl & (1u << (2 * r)))     { mn1 = min(mn1, rr); mx1 = max(mx1, rr); }
            if (fl & (1u << (2 * r + 1))) { mn2 = min(mn2, rr); mx2 = max(mx2, rr); }
        }
    }

    __shared__ float ra[256], rb[256];
    __shared__ int   ja[256], jb[256], jc[256], jd[256];
    ra[tid] = v1;  rb[tid] = v2;
    ja[tid] = mn1; jb[tid] = mx1; jc[tid] = mn2; jd[tid] = mx2;
    __syncthreads();
#pragma unroll
    for (int s = 128; s > 0; s >>= 1) {
        if (tid < s) {
            ra[tid] += ra[tid + s];
            rb[tid] += rb[tid + s];
            ja[tid] = min(ja[tid], ja[tid + s]);
            jb[tid] = max(jb[tid], jb[tid + s]);
            jc[tid] = min(jc[tid], jc[tid + s]);
            jd[tid] = max(jd[tid], jd[tid + s]);
        }
        __syncthreads();
    }

    if (tid == 0) {
        const float inv_hw = 1.0f / (float)HWn;
        float cup_mean  = ra[0] * inv_hw;
        float disc_mean = rb[0] * inv_hw;
        float hcup  = (jb[0] >= 0) ? (float)(jb[0] - ja[0]) : 0.0f;
        float hdisc = (jd[0] >= 0) ? (float)(jd[0] - jc[0]) : 0.0f;
        float cdr = hcup / (hdisc + 1e-6f);
        out[b * 5 + 0] = cdr;
        out[b * 5 + 1] = disc_mean;
        out[b * 5 + 2] = cup_mean;
        out[b * 5 + 3] = disc_mean;
        out[b * 5 + 4] = cup_mean;
        g_count[b] = 0;   // self-reset: deterministic across graph replays
    }
}

extern "C" void kernel_launch(void* const* d_in, const int* in_sizes, int n_in,
                              void* d_out, int out_size) {
    const float* x = (const float*)d_in[0];
    float* out = (float*)d_out;
    (void)in_sizes; (void)n_in; (void)out_size;

    cdr_fused_kernel<<<GRID, 256>>>(x, out);
}

// round 4
// speedup vs baseline: 1.0164x; 1.0164x over previous
#include <cuda_runtime.h>
#include <climits>

#define Bn 64
#define Hn 512
#define Wn 512
#define HWn (Hn * Wn)
#define HW4 (HWn / 4)
#define BLOCKS_PER_BATCH 128          // 4 rows per block
#define GRID (Bn * BLOCKS_PER_BATCH)  // 8192

// Per-block partials — fully overwritten every launch before being read.
// Counter self-resets (last block zeroes it): deterministic across replays.
__device__ float    g_ps1[GRID];
__device__ float    g_ps2[GRID];
__device__ unsigned g_pflags[GRID];
__device__ unsigned g_count[Bn];

__global__ void __launch_bounds__(256) cdr_fused_kernel(const float* __restrict__ x,
                                                        float* __restrict__ out) {
    const int b       = blockIdx.x >> 7;    // batch
    const int rowpair = blockIdx.x & 127;   // which pair of rows (4 rows/block)
    const int tid     = threadIdx.x;
    const int rsel    = tid >> 7;           // 0 or 1
    const int row     = rowpair * 2 + rsel; // NOTE: rows covered = rowpair*2 .. +1 per half,
    const int c4      = tid & 127;          // plus second float4 batch covers rows +2 via offset

    // Block covers 4 rows: threads map rows {4q, 4q+1} in batch A and {4q+2, 4q+3} in batch B.
    const int rA = rowpair * 4 + rsel * 2;  // row for first float4 triple (even rows)
    // second triple is row rA+1 (base + 128 float4s = +512 floats = next row)
    (void)row;

    const float4* p = (const float4*)x;
    const size_t base4 = (((size_t)b * 3 * HWn + (size_t)rA * Wn) >> 2) + (size_t)c4;
    // 6 front-batched coalesced LDG.128
    float4 v0a = p[base4];
    float4 v1a = p[base4 + HW4];
    float4 v2a = p[base4 + 2 * HW4];
    float4 v0b = p[base4 + 128];            // row rA+1
    float4 v1b = p[base4 + HW4 + 128];
    float4 v2b = p[base4 + 2 * HW4 + 128];

    float s1 = 0.f, s2 = 0.f;
    bool anyA1 = false, anyA2 = false, anyB1 = false, anyB2 = false;

    // ---- group A (row rA): 4 px, one batched reciprocal ----
    {
        const float* a0 = (const float*)&v0a;
        const float* a1 = (const float*)&v1a;
        const float* a2 = (const float*)&v2a;
        float d[4], e2v[4];
#pragma unroll
        for (int k = 0; k < 4; k++) {
            float x0 = a0[k], x1 = a1[k], x2 = a2[k];
            float m01 = fmaxf(x0, x1);
            bool  l1  = x1 > x0;
            bool  l2  = x2 > m01;
            anyA1 |= (l1 && !l2);
            anyA2 |= l2;
            float e0 = __expf(x0 - x1);
            float e2 = __expf(x2 - x1);
            e2v[k] = e2;
            d[k]   = e0 + 1.0f + e2;
        }
        float d01 = d[0] * d[1], d23 = d[2] * d[3];
        float r   = __fdividef(1.0f, d01 * d23);   // single RCP for 4 pixels
        float r01 = r * d23, r23 = r * d01;
        float i0 = r01 * d[1], i1 = r01 * d[0];
        float i2 = r23 * d[3], i3 = r23 * d[2];
        s1 += (i0 + i1) + (i2 + i3);
        s2 += (e2v[0] * i0 + e2v[1] * i1) + (e2v[2] * i2 + e2v[3] * i3);
    }

    // ---- group B (row rA+1): 4 px, one batched reciprocal ----
    {
        const float* a0 = (const float*)&v0b;
        const float* a1 = (const float*)&v1b;
        const float* a2 = (const float*)&v2b;
        float d[4], e2v[4];
#pragma unroll
        for (int k = 0; k < 4; k++) {
            float x0 = a0[k], x1 = a1[k], x2 = a2[k];
            float m01 = fmaxf(x0, x1);
            bool  l1  = x1 > x0;
            bool  l2  = x2 > m01;
            anyB1 |= (l1 && !l2);
            anyB2 |= l2;
            float e0 = __expf(x0 - x1);
            float e2 = __expf(x2 - x1);
            e2v[k] = e2;
            d[k]   = e0 + 1.0f + e2;
        }
        float d01 = d[0] * d[1], d23 = d[2] * d[3];
        float r   = __fdividef(1.0f, d01 * d23);
        float r01 = r * d23, r23 = r * d01;
        float i0 = r01 * d[1], i1 = r01 * d[0];
        float i2 = r23 * d[3], i3 = r23 * d[2];
        s1 += (i0 + i1) + (i2 + i3);
        s2 += (e2v[0] * i0 + e2v[1] * i1) + (e2v[2] * i2 + e2v[3] * i3);
    }

    // ---- deterministic in-warp reduction ----
#pragma unroll
    for (int o = 16; o > 0; o >>= 1) {
        s1 += __shfl_xor_sync(0xFFFFFFFFu, s1, o);
        s2 += __shfl_xor_sync(0xFFFFFFFFu, s2, o);
    }
    // flags: rows rA (bitpair 0) and rA+1 (bitpair 1), per warp
    unsigned wf = (__any_sync(0xFFFFFFFFu, anyA1) ? 1u : 0u)
                | (__any_sync(0xFFFFFFFFu, anyA2) ? 2u : 0u)
                | (__any_sync(0xFFFFFFFFu, anyB1) ? 4u : 0u)
                | (__any_sync(0xFFFFFFFFu, anyB2) ? 8u : 0u);

    __shared__ float    sw1[8], sw2[8];
    __shared__ unsigned swf[8];
    const int wid = tid >> 5, lid = tid & 31;
    if (lid == 0) { sw1[wid] = s1; sw2[wid] = s2; swf[wid] = wf; }
    __syncthreads();

    if (tid == 0) {
        float bs1 = 0.f, bs2 = 0.f;
#pragma unroll
        for (int w = 0; w < 8; w++) { bs1 += sw1[w]; bs2 += sw2[w]; }
        // warps 0..3 handled rows {4q,4q+1}; warps 4..7 rows {4q+2,4q+3}
        unsigned fLo = swf[0] | swf[1] | swf[2] | swf[3];   // bits0,1: row0; bits2,3: row1
        unsigned fHi = swf[4] | swf[5] | swf[6] | swf[7];   // bits0,1: row2; bits2,3: row3
        // pack 4 rows x 2 labels -> 8 bits: row r -> bits 2r (cup), 2r+1 (disc)
        unsigned fw = (fLo & 0xFu) | ((fHi & 0xFu) << 4);
        g_ps1[blockIdx.x]    = bs1;
        g_ps2[blockIdx.x]    = bs2;
        g_pflags[blockIdx.x] = fw;
    }

    // ---- last block of each batch finalizes ----
    __shared__ int lastFlag;
    if (tid == 0) {
        __threadfence();
        lastFlag = (atomicAdd(&g_count[b], 1u) == BLOCKS_PER_BATCH - 1);
    }
    __syncthreads();
    if (!lastFlag) return;

    float v1 = 0.f, v2 = 0.f;
    int   mn1 = INT_MAX, mx1 = -1, mn2 = INT_MAX, mx2 = -1;
    if (tid < BLOCKS_PER_BATCH) {
        int idx = b * BLOCKS_PER_BATCH + tid;
        v1 = g_ps1[idx];
        v2 = g_ps2[idx];
        unsigned fl = g_pflags[idx];
#pragma unroll
        for (int r = 0; r < 4; r++) {
            int rr = tid * 4 + r;
            if (fl & (1u << (2 * r)))     { mn1 = min(mn1, rr); mx1 = max(mx1, rr); }
            if (fl & (1u << (2 * r + 1))) { mn2 = min(mn2, rr); mx2 = max(mx2, rr); }
        }
    }

    __shared__ float ra[256], rb[256];
    __shared__ int   ja[256], jb[256], jc[256], jd[256];
    ra[tid] = v1;  rb[tid] = v2;
    ja[tid] = mn1; jb[tid] = mx1; jc[tid] = mn2; jd[tid] = mx2;
    __syncthreads();
#pragma unroll
    for (int s = 128; s > 0; s >>= 1) {
        if (tid < s) {
            ra[tid] += ra[tid + s];
            rb[tid] += rb[tid + s];
            ja[tid] = min(ja[tid], ja[tid + s]);
            jb[tid] = max(jb[tid], jb[tid + s]);
            jc[tid] = min(jc[tid], jc[tid + s]);
            jd[tid] = max(jd[tid], jd[tid + s]);
        }
        __syncthreads();
    }

    if (tid == 0) {
        const float inv_hw = 1.0f / (float)HWn;
        float cup_mean  = ra[0] * inv_hw;
        float disc_mean = rb[0] * inv_hw;
        float hcup  = (jb[0] >= 0) ? (float)(jb[0] - ja[0]) : 0.0f;
        float hdisc = (jd[0] >= 0) ? (float)(jd[0] - jc[0]) : 0.0f;
        float cdr = hcup / (hdisc + 1e-6f);
        out[b * 5 + 0] = cdr;
        out[b * 5 + 1] = disc_mean;
        out[b * 5 + 2] = cup_mean;
        out[b * 5 + 3] = disc_mean;
        out[b * 5 + 4] = cup_mean;
        g_count[b] = 0;   // self-reset: deterministic across graph replays
    }
}

extern "C" void kernel_launch(void* const* d_in, const int* in_sizes, int n_in,
                              void* d_out, int out_size) {
    const float* x = (const float*)d_in[0];
    float* out = (float*)d_out;
    (void)in_sizes; (void)n_in; (void)out_size;

    cdr_fused_kernel<<<GRID, 256>>>(x, out);
}

// round 5
// speedup vs baseline: 1.1142x; 1.0962x over previous
#include <cuda_runtime.h>
#include <climits>

#define Bn 64
#define Hn 512
#define Wn 512
#define HWn (Hn * Wn)
#define HW4 (HWn / 4)
#define BLOCKS_PER_BATCH 128          // 4 rows per block
#define GRID (Bn * BLOCKS_PER_BATCH)  // 8192

// Per-block partials — fully overwritten every launch before being read.
// Counter self-resets (elected warp zeroes it): deterministic across replays.
__device__ float    g_ps1[GRID];
__device__ float    g_ps2[GRID];
__device__ unsigned g_pflags[GRID];   // 8 bits: row r (0..3) -> bits 2r (cup), 2r+1 (disc)
__device__ unsigned g_count[Bn];

__global__ void __launch_bounds__(256) cdr_fused_kernel(const float* __restrict__ x,
                                                        float* __restrict__ out) {
    const int b    = blockIdx.x >> 7;     // batch
    const int quad = blockIdx.x & 127;    // group of 4 rows
    const int tid  = threadIdx.x;
    const int rsel = tid >> 7;            // 0: rows {4q,4q+1}, 1: rows {4q+2,4q+3}
    const int c4   = tid & 127;
    const int rA   = quad * 4 + rsel * 2;

    // ---- Phase 1: 6 front-batched coalesced LDG.128 ----
    const float4* p = (const float4*)x;
    const size_t base4 = (((size_t)b * 3 * HWn + (size_t)rA * Wn) >> 2) + (size_t)c4;
    float4 v0a = p[base4];
    float4 v1a = p[base4 + HW4];
    float4 v2a = p[base4 + 2 * HW4];
    float4 v0b = p[base4 + 128];          // row rA+1
    float4 v1b = p[base4 + HW4 + 128];
    float4 v2b = p[base4 + 2 * HW4 + 128];

    float s1 = 0.f, s2 = 0.f;
    bool anyA1 = false, anyA2 = false, anyB1 = false, anyB2 = false;

    const float* f0 = (const float*)&v0a;
    const float* f1 = (const float*)&v1a;
    const float* f2 = (const float*)&v2a;
    const float* h0 = (const float*)&v0b;
    const float* h1 = (const float*)&v1b;
    const float* h2 = (const float*)&v2b;

#pragma unroll
    for (int k = 0; k < 4; k++) {
        float a0 = f0[k], a1 = f1[k], a2 = f2[k];
        float m01 = fmaxf(a0, a1);
        bool  l1  = a1 > a0;
        bool  l2  = a2 > m01;
        anyA1 |= (l1 && !l2);
        anyA2 |= l2;
        float e0  = __expf(a0 - a1);
        float e2  = __expf(a2 - a1);
        float inv = __fdividef(1.0f, e0 + 1.0f + e2);
        s1 += inv;
        s2 += e2 * inv;
    }
#pragma unroll
    for (int k = 0; k < 4; k++) {
        float a0 = h0[k], a1 = h1[k], a2 = h2[k];
        float m01 = fmaxf(a0, a1);
        bool  l1  = a1 > a0;
        bool  l2  = a2 > m01;
        anyB1 |= (l1 && !l2);
        anyB2 |= l2;
        float e0  = __expf(a0 - a1);
        float e2  = __expf(a2 - a1);
        float inv = __fdividef(1.0f, e0 + 1.0f + e2);
        s1 += inv;
        s2 += e2 * inv;
    }

    // ---- Phase 2: deterministic in-warp reduction ----
#pragma unroll
    for (int o = 16; o > 0; o >>= 1) {
        s1 += __shfl_xor_sync(0xFFFFFFFFu, s1, o);
        s2 += __shfl_xor_sync(0xFFFFFFFFu, s2, o);
    }
    // per-warp flags for its two rows (row rA -> bits 0/1, row rA+1 -> bits 2/3)
    unsigned wf = (__any_sync(0xFFFFFFFFu, anyA1) ? 1u : 0u)
                | (__any_sync(0xFFFFFFFFu, anyA2) ? 2u : 0u)
                | (__any_sync(0xFFFFFFFFu, anyB1) ? 4u : 0u)
                | (__any_sync(0xFFFFFFFFu, anyB2) ? 8u : 0u);

    __shared__ float    sw1[8], sw2[8];
    __shared__ unsigned swf[8];
    const int wid = tid >> 5, lid = tid & 31;
    if (lid == 0) { sw1[wid] = s1; sw2[wid] = s2; swf[wid] = wf; }
    __syncthreads();

    // 7 of 8 warps retire immediately — their SM slots go to the next block's loads.
    if (wid != 0) return;

    // ---- Phase 3: warp 0 only, warp-synchronous from here ----
    float pv1 = (lid < 8) ? sw1[lid] : 0.f;
    float pv2 = (lid < 8) ? sw2[lid] : 0.f;
    unsigned pf = (lid < 8) ? swf[lid] : 0u;
#pragma unroll
    for (int o = 4; o > 0; o >>= 1) {
        pv1 += __shfl_xor_sync(0xFFFFFFFFu, pv1, o);
        pv2 += __shfl_xor_sync(0xFFFFFFFFu, pv2, o);
        pf  |= __shfl_xor_sync(0xFFFFFFFFu, pf, o);
    }
    // lanes 0..7 held warps 0..7; after xor-4,2,1 reduce, lane0 has warps 0..7? No:
    // xor over lanes 0..31 with pads=0 sums all 8 live entries into every lane. OK.

    int lastFlag = 0;
    if (lid == 0) {
        // warps 0-3 handled rows {4q,4q+1} (bits 0-3), warps 4-7 rows {4q+2,4q+3}.
        // pf merged all 8 warps, so bits 0-3 hold OR over both halves — need split.
        // Recompute split merge from shared (cheap, 8 LDS):
        unsigned fLo = swf[0] | swf[1] | swf[2] | swf[3];
        unsigned fHi = swf[4] | swf[5] | swf[6] | swf[7];
        unsigned fw  = (fLo & 0xFu) | ((fHi & 0xFu) << 4);
        g_ps1[blockIdx.x]    = pv1;
        g_ps2[blockIdx.x]    = pv2;
        g_pflags[blockIdx.x] = fw;
        __threadfence();
        lastFlag = (atomicAdd(&g_count[b], 1u) == BLOCKS_PER_BATCH - 1);
    }
    lastFlag = __shfl_sync(0xFFFFFFFFu, lastFlag, 0);
    if (!lastFlag) return;

    // ---- Phase 4: elected warp finalizes batch b (128 partials, 4 per lane) ----
    float t1 = 0.f, t2 = 0.f;
    int mn1 = INT_MAX, mx1 = -1, mn2 = INT_MAX, mx2 = -1;
#pragma unroll
    for (int j = 0; j < 4; j++) {
        int e   = lid + 32 * j;                  // block index within batch
        int idx = b * BLOCKS_PER_BATCH + e;
        t1 += g_ps1[idx];
        t2 += g_ps2[idx];
        unsigned fl = g_pflags[idx];
#pragma unroll
        for (int r = 0; r < 4; r++) {
            int rr = e * 4 + r;
            if (fl & (1u << (2 * r)))     { mn1 = min(mn1, rr); mx1 = max(mx1, rr); }
            if (fl & (1u << (2 * r + 1))) { mn2 = min(mn2, rr); mx2 = max(mx2, rr); }
        }
    }
#pragma unroll
    for (int o = 16; o > 0; o >>= 1) {
        t1  += __shfl_xor_sync(0xFFFFFFFFu, t1, o);
        t2  += __shfl_xor_sync(0xFFFFFFFFu, t2, o);
        mn1  = min(mn1, __shfl_xor_sync(0xFFFFFFFFu, mn1, o));
        mx1  = max(mx1, __shfl_xor_sync(0xFFFFFFFFu, mx1, o));
        mn2  = min(mn2, __shfl_xor_sync(0xFFFFFFFFu, mn2, o));
        mx2  = max(mx2, __shfl_xor_sync(0xFFFFFFFFu, mx2, o));
    }

    if (lid == 0) {
        const float inv_hw = 1.0f / (float)HWn;
        float cup_mean  = t1 * inv_hw;
        float disc_mean = t2 * inv_hw;
        float hcup  = (mx1 >= 0) ? (float)(mx1 - mn1) : 0.0f;
        float hdisc = (mx2 >= 0) ? (float)(mx2 - mn2) : 0.0f;
        float cdr = hcup / (hdisc + 1e-6f);
        out[b * 5 + 0] = cdr;
        out[b * 5 + 1] = disc_mean;
        out[b * 5 + 2] = cup_mean;
        out[b * 5 + 3] = disc_mean;
        out[b * 5 + 4] = cup_mean;
        g_count[b] = 0;   // self-reset: deterministic across graph replays
    }
}

extern "C" void kernel_launch(void* const* d_in, const int* in_sizes, int n_in,
                              void* d_out, int out_size) {
    const float* x = (const float*)d_in[0];
    float* out = (float*)d_out;
    (void)in_sizes; (void)n_in; (void)out_size;

    cdr_fused_kernel<<<GRID, 256>>>(x, out);
}